// round 3
// baseline (speedup 1.0000x reference)
#include <cuda_runtime.h>

// Reverse (suffix) cummax along axis 1 of [B=16, H=128, W=128, C=256] fp32.
// One thread per (b, w, c4) float4-column; walk h from H-1 down to 0 keeping a
// running componentwise max. Loads/stores are fully coalesced (consecutive
// threads -> consecutive c). Loads are address-independent across h, so the
// unrolled loop builds MLP; only the fmaxf chain is serial (lat 4, hidden).

#define B_DIM 16
#define H_DIM 128
#define W_DIM 128
#define C_DIM 256

#define C4      (C_DIM / 4)          // 64 float4 per row in C
#define STRIDE4 (W_DIM * C4)         // 8192 float4 between consecutive h
#define NCOLS   (B_DIM * W_DIM * C4) // 131072 independent columns

__global__ void __launch_bounds__(256)
leftpool_rev_cummax_kernel(const float4* __restrict__ in,
                           float4* __restrict__ out) {
    const int tid = blockIdx.x * blockDim.x + threadIdx.x;
    if (tid >= NCOLS) return;

    // tid = b * (W*C4) + (w*C4 + c4)
    const int b   = tid / (W_DIM * C4);
    const int rem = tid - b * (W_DIM * C4);

    // base offset (in float4 units) of (b, h=0, w, c4)
    const int base = b * (H_DIM * STRIDE4) + rem;

    // h = H-1: copy through
    int off = base + (H_DIM - 1) * STRIDE4;
    float4 m = in[off];
    out[off] = m;

    // h = H-2 .. 0: running suffix max
    #pragma unroll 4
    for (int h = H_DIM - 2; h >= 0; --h) {
        off -= STRIDE4;
        const float4 v = in[off];
        m.x = fmaxf(m.x, v.x);
        m.y = fmaxf(m.y, v.y);
        m.z = fmaxf(m.z, v.z);
        m.w = fmaxf(m.w, v.w);
        out[off] = m;
    }
}

extern "C" void kernel_launch(void* const* d_in, const int* in_sizes, int n_in,
                              void* d_out, int out_size) {
    const float4* in  = (const float4*)d_in[0];
    float4*       out = (float4*)d_out;

    const int threads = 256;
    const int blocks  = (NCOLS + threads - 1) / threads; // 512
    leftpool_rev_cummax_kernel<<<blocks, threads>>>(in, out);
}

// round 5
// speedup vs baseline: 1.0179x; 1.0179x over previous
#include <cuda_runtime.h>

// Reverse (suffix) cummax along axis 1 of [B=16, H=128, W=128, C=256] fp32.
// One thread per (b, w, c4) float4-column, walking h top-down with a running
// componentwise max. Fully coalesced 128B warp transactions at every h.
//
// R3 changes vs R2:
//  - block 256 -> 128: 1024 blocks over 148 SMs = 6.92 blocks/SM, so the
//    busiest SM carries 896 threads vs 886 average (1.2% imbalance) instead
//    of the 512-block layout's 1024 vs 886 (15.6%). Kills the low-BW tail
//    phase that held DRAM at 74.1%.
//  - unroll 8 + no bounds check: 8 address-independent LDG.128 batched ahead
//    of the dependent max/store chain (loads can hoist past stores thanks to
//    __restrict__), doubling per-thread loads in flight.

#define B_DIM 16
#define H_DIM 128
#define W_DIM 128
#define C_DIM 256

#define C4      (C_DIM / 4)          // 64 float4 per row in C
#define STRIDE4 (W_DIM * C4)         // 8192 float4 between consecutive h
#define NCOLS   (B_DIM * W_DIM * C4) // 131072 independent columns

#define THREADS 128
#define BLOCKS  (NCOLS / THREADS)    // 1024, exact

__global__ void __launch_bounds__(THREADS)
leftpool_rev_cummax_kernel(const float4* __restrict__ in,
                           float4* __restrict__ out) {
    const int tid = blockIdx.x * THREADS + threadIdx.x;  // always < NCOLS

    // tid = b * (W*C4) + rem
    const int b   = tid / (W_DIM * C4);
    const int rem = tid - b * (W_DIM * C4);

    // offset (in float4 units) of (b, h=H-1, w, c4)
    int off = b * (H_DIM * STRIDE4) + rem + (H_DIM - 1) * STRIDE4;

    // h = H-1: copy through
    float4 m = in[off];
    out[off] = m;

    // Peel 7 iterations so the remaining 120 unroll cleanly by 8.
    #pragma unroll
    for (int i = 0; i < 7; ++i) {
        off -= STRIDE4;
        const float4 v = in[off];
        m.x = fmaxf(m.x, v.x);
        m.y = fmaxf(m.y, v.y);
        m.z = fmaxf(m.z, v.z);
        m.w = fmaxf(m.w, v.w);
        out[off] = m;
    }

    // h = H-9 .. 0 in unroll-8 batches: 8 independent loads issue together,
    // then the serial max chain + 8 stores.
    #pragma unroll 1
    for (int hblk = 0; hblk < (H_DIM - 8) / 8; ++hblk) {
        float4 v[8];
        #pragma unroll
        for (int i = 0; i < 8; ++i)
            v[i] = in[off - (i + 1) * STRIDE4];

        #pragma unroll
        for (int i = 0; i < 8; ++i) {
            m.x = fmaxf(m.x, v[i].x);
            m.y = fmaxf(m.y, v[i].y);
            m.z = fmaxf(m.z, v[i].z);
            m.w = fmaxf(m.w, v[i].w);
            out[off - (i + 1) * STRIDE4] = m;
        }
        off -= 8 * STRIDE4;
    }
}

extern "C" void kernel_launch(void* const* d_in, const int* in_sizes, int n_in,
                              void* d_out, int out_size) {
    const float4* in  = (const float4*)d_in[0];
    float4*       out = (float4*)d_out;
    leftpool_rev_cummax_kernel<<<BLOCKS, THREADS>>>(in, out);
}

// round 7
// speedup vs baseline: 1.1238x; 1.1040x over previous
#include <cuda_runtime.h>

// Reverse (suffix) cummax along axis 1 of [B=16, H=128, W=128, C=256] fp32.
//
// R5: register-blocked segmented scan to burst-separate the HBM read stream
// from the write stream (R3's interleaved load/store pairs held DRAM at 77%).
//
//  - Thread owns a 16-element h-segment of one float4 column (64 regs of data).
//  - Block = 256 thr = 8 segments x 32 c4-lanes  -> one (b, w, c4-half) slab,
//    i.e. the full H=128 column for 32 adjacent float4 columns.
//  - Phase 1: 16 coalesced 512B/warp loads (independent -> 16-deep MLP).
//  - Phase 2: in-register local suffix max; per-segment maxes exchanged via
//    4KB smem; fold in carry = max of all later segments.
//  - Phase 3: 16 coalesced 512B/warp stores.
//  Traffic stays exactly read-once / write-once (512 MB total).

#define B_DIM 16
#define H_DIM 128
#define W_DIM 128
#define C_DIM 256

#define C4      (C_DIM / 4)     // 64 float4 per (b,h,w) row
#define STRIDE4 (W_DIM * C4)    // 8192 float4 between consecutive h

#define SEG_LEN  16             // h elements per thread
#define NSEG     (H_DIM / SEG_LEN)   // 8 segments per column
#define LANES    32              // c4 lanes per block (half of C4)
#define THREADS  (NSEG * LANES)  // 256
#define BLOCKS   (B_DIM * W_DIM * (C4 / LANES))  // 4096

__device__ __forceinline__ float4 f4max(float4 a, float4 b) {
    float4 r;
    r.x = fmaxf(a.x, b.x);
    r.y = fmaxf(a.y, b.y);
    r.z = fmaxf(a.z, b.z);
    r.w = fmaxf(a.w, b.w);
    return r;
}

__global__ void __launch_bounds__(THREADS, 2)
leftpool_rev_cummax_seg_kernel(const float4* __restrict__ in,
                               float4* __restrict__ out) {
    __shared__ float4 segmax[NSEG * LANES];   // 4 KB

    const int seg  = threadIdx.x >> 5;        // 0..7  (warp id)
    const int lane = threadIdx.x & 31;        // 0..31 (c4 within half)

    // blockIdx.x = (b * W + w) * 2 + half
    const int half = blockIdx.x & 1;
    const int bw   = blockIdx.x >> 1;         // b*W + w
    const int c4   = half * LANES + lane;

    // float4 offset of (b, h, w, c4) = (bw_b*H + h)*STRIDE4_row... expand:
    // ((b*H + h)*W + w)*C4 + c4 ; with b = bw / W, w = bw % W.
    const int b = bw / W_DIM;
    const int w = bw - b * W_DIM;
    const int base = ((b * H_DIM + seg * SEG_LEN) * W_DIM + w) * C4 + c4;

    // ---- Phase 1: burst load my segment (16 independent coalesced loads)
    float4 v[SEG_LEN];
    #pragma unroll
    for (int i = 0; i < SEG_LEN; ++i)
        v[i] = __ldcs(&in[base + i * STRIDE4]);

    // ---- Phase 2a: local (within-segment) suffix max, in registers
    #pragma unroll
    for (int i = SEG_LEN - 2; i >= 0; --i)
        v[i] = f4max(v[i], v[i + 1]);

    // segment total max = v[0]
    segmax[seg * LANES + lane] = v[0];
    __syncthreads();

    // ---- Phase 2b: carry = max over all later segments (same column)
    float4 carry;
    carry.x = carry.y = carry.z = carry.w = __int_as_float(0xff800000); // -inf
    for (int s = seg + 1; s < NSEG; ++s)              // uniform per warp
        carry = f4max(carry, segmax[s * LANES + lane]);

    #pragma unroll
    for (int i = 0; i < SEG_LEN; ++i)
        v[i] = f4max(v[i], carry);

    // ---- Phase 3: burst store (16 coalesced streaming stores)
    #pragma unroll
    for (int i = 0; i < SEG_LEN; ++i)
        __stcs(&out[base + i * STRIDE4], v[i]);
}

extern "C" void kernel_launch(void* const* d_in, const int* in_sizes, int n_in,
                              void* d_out, int out_size) {
    const float4* in  = (const float4*)d_in[0];
    float4*       out = (float4*)d_out;
    leftpool_rev_cummax_seg_kernel<<<BLOCKS, THREADS>>>(in, out);
}

// round 8
// speedup vs baseline: 1.1282x; 1.0039x over previous
#include <cuda_runtime.h>

// Reverse (suffix) cummax along axis 1 of [B=16, H=128, W=128, C=256] fp32.
//
// R7: same burst-separated segmented scan as R5, but SEG_LEN 16->8 /
// NSEG 8->16 / block 512 threads. Halving per-thread register data (64->32
// regs) lets 2x512-thread blocks co-reside -> 32 warps/SM (occ 50%, double
// R5's 16). Theory: R5's DRAM 78.5% was capped by outstanding-request
// concurrency (during a block's store phase no loads issue; only 2 blocks/SM
// to overlap), not by read/write turnaround.
//
//  - Thread owns an 8-element h-segment of one float4 column.
//  - Block = 512 thr = 16 segments (warps) x 32 c4-lanes: full H=128 column
//    for 32 adjacent float4 columns.
//  - Phase 1: 8 independent coalesced 512B/warp loads.
//  - Phase 2: in-register local suffix max; per-segment maxes via 8KB smem;
//    fold in carry = max of all later segments.
//  - Phase 3: 8 coalesced 512B/warp streaming stores.
//  Traffic stays exactly read-once / write-once (512 MB total).

#define B_DIM 16
#define H_DIM 128
#define W_DIM 128
#define C_DIM 256

#define C4      (C_DIM / 4)     // 64 float4 per (b,h,w) row
#define STRIDE4 (W_DIM * C4)    // 8192 float4 between consecutive h

#define SEG_LEN  8                   // h elements per thread
#define NSEG     (H_DIM / SEG_LEN)   // 16 segments per column
#define LANES    32                  // c4 lanes per block (half of C4)
#define THREADS  (NSEG * LANES)      // 512
#define BLOCKS   (B_DIM * W_DIM * (C4 / LANES))  // 4096

__device__ __forceinline__ float4 f4max(float4 a, float4 b) {
    float4 r;
    r.x = fmaxf(a.x, b.x);
    r.y = fmaxf(a.y, b.y);
    r.z = fmaxf(a.z, b.z);
    r.w = fmaxf(a.w, b.w);
    return r;
}

__global__ void __launch_bounds__(THREADS, 2)
leftpool_rev_cummax_seg8_kernel(const float4* __restrict__ in,
                                float4* __restrict__ out) {
    __shared__ float4 segmax[NSEG * LANES];   // 8 KB

    const int seg  = threadIdx.x >> 5;        // 0..15 (warp id = segment)
    const int lane = threadIdx.x & 31;        // 0..31 (c4 within half)

    // blockIdx.x = (b * W + w) * 2 + half
    const int half = blockIdx.x & 1;
    const int bw   = blockIdx.x >> 1;         // b*W + w
    const int c4   = half * LANES + lane;

    const int b = bw / W_DIM;
    const int w = bw - b * W_DIM;
    // float4 offset of (b, h = seg*SEG_LEN, w, c4)
    const int base = ((b * H_DIM + seg * SEG_LEN) * W_DIM + w) * C4 + c4;

    // ---- Phase 1: burst load my segment (8 independent coalesced loads)
    float4 v[SEG_LEN];
    #pragma unroll
    for (int i = 0; i < SEG_LEN; ++i)
        v[i] = __ldcs(&in[base + i * STRIDE4]);

    // ---- Phase 2a: local (within-segment) suffix max, in registers
    #pragma unroll
    for (int i = SEG_LEN - 2; i >= 0; --i)
        v[i] = f4max(v[i], v[i + 1]);

    segmax[seg * LANES + lane] = v[0];
    __syncthreads();

    // ---- Phase 2b: carry = max over all later segments (same column)
    float4 carry;
    carry.x = carry.y = carry.z = carry.w = __int_as_float(0xff800000); // -inf
    for (int s = seg + 1; s < NSEG; ++s)              // uniform per warp
        carry = f4max(carry, segmax[s * LANES + lane]);

    #pragma unroll
    for (int i = 0; i < SEG_LEN; ++i)
        v[i] = f4max(v[i], carry);

    // ---- Phase 3: burst store (8 coalesced streaming stores)
    #pragma unroll
    for (int i = 0; i < SEG_LEN; ++i)
        __stcs(&out[base + i * STRIDE4], v[i]);
}

extern "C" void kernel_launch(void* const* d_in, const int* in_sizes, int n_in,
                              void* d_out, int out_size) {
    const float4* in  = (const float4*)d_in[0];
    float4*       out = (float4*)d_out;
    leftpool_rev_cummax_seg8_kernel<<<BLOCKS, THREADS>>>(in, out);
}